// round 5
// baseline (speedup 1.0000x reference)
#include <cuda_runtime.h>
#include <cuda_bf16.h>
#include <cstdint>

#define CDIM    128
#define NEXP    8
#define SPATIAL 32768
#define NVOX    65536
#define CHUNK   512
#define NCHUNK  128
#define SUBV    128
#define PKB     272           // expert smem tile row pitch (bytes)
#define VP      65            // gate smem [c][v] pitch (floats)

// ---------------- device scratch ----------------
__device__ __nv_bfloat16 g_xbt[(size_t)NVOX * CDIM];   // x, bf16, [v][c]
__device__ __nv_bfloat16 g_y0h[(size_t)CDIM * NVOX];   // slot-0 y, bf16, [c][vglobal]
__device__ __nv_bfloat16 g_y1h[(size_t)CDIM * NVOX];   // slot-1 y, bf16, [c][vglobal]
__device__ unsigned short g_route[NVOX];
__device__ float          g_prob[NVOX];

__device__ __forceinline__ uint32_t smem_u32(const void* p) {
    uint32_t a;
    asm("{ .reg .u64 t; cvta.to.shared.u64 t, %1; cvt.u32.u64 %0, t; }" : "=r"(a) : "l"(p));
    return a;
}

#define LDSM_X4(r0, r1, r2, r3, addr) \
    asm volatile("ldmatrix.sync.aligned.m8n8.x4.shared.b16 {%0,%1,%2,%3}, [%4];" \
        : "=r"(r0), "=r"(r1), "=r"(r2), "=r"(r3) : "r"(addr))

#define MMA16816(c, a, b) \
    asm volatile("mma.sync.aligned.m16n8k16.row.col.f32.bf16.bf16.f32 " \
        "{%0,%1,%2,%3}, {%4,%5,%6,%7}, {%8,%9}, {%0,%1,%2,%3};" \
        : "+f"((c)[0]), "+f"((c)[1]), "+f"((c)[2]), "+f"((c)[3]) \
        : "r"((a)[0]), "r"((a)[1]), "r"((a)[2]), "r"((a)[3]), "r"((b)[0]), "r"((b)[1]))

// ================= K1: gate + bf16 xT emission =================
__global__ __launch_bounds__(256)
void gate_kernel(const float* __restrict__ x,
                 const float* __restrict__ gw,
                 const float* __restrict__ gb)
{
    __shared__ float xs[CDIM * VP];       // [c][v] pitch 65 -> conflict-free everywhere
    __shared__ float gws[NEXP * CDIM];
    __shared__ float lgs[64 * NEXP];

    const int tid = threadIdx.x;
    const int vg0 = blockIdx.x * 64;
    const int b = vg0 >> 15, s0 = vg0 & (SPATIAL - 1);
    const float* xb = x + ((size_t)b * CDIM) * SPATIAL + s0;

    for (int i = tid; i < NEXP * CDIM; i += 256) gws[i] = gw[i];

    const int c_sub = tid >> 6, iv = tid & 63;
    #pragma unroll
    for (int cc = 0; cc < CDIM; cc += 4) {
        int c = cc + c_sub;
        xs[c * VP + iv] = xb[(size_t)c * SPATIAL + iv];
    }
    __syncthreads();

    // logits: thread owns (v, experts es & es+4)
    {
        int v = tid & 63, es = tid >> 6;
        const float* g0 = gws + es * CDIM;
        const float* g1 = gws + (es + 4) * CDIM;
        float a0 = 0.f, a1 = 0.f;
        #pragma unroll 8
        for (int k = 0; k < CDIM; k++) {
            float xv = xs[k * VP + v];
            a0 = fmaf(xv, g0[k], a0);
            a1 = fmaf(xv, g1[k], a1);
        }
        lgs[v * NEXP + es]     = a0 + __ldg(gb + es);
        lgs[v * NEXP + es + 4] = a1 + __ldg(gb + es + 4);
    }
    __syncthreads();

    if (tid < 64) {
        const float* l = lgs + tid * NEXP;
        int i0 = 0; float v0 = l[0];
        #pragma unroll
        for (int e = 1; e < NEXP; e++) { float t = l[e]; if (t > v0) { v0 = t; i0 = e; } }
        int i1 = -1; float v1 = -3.4e38f;
        #pragma unroll
        for (int e = 0; e < NEXP; e++) {
            if (e == i0) continue;
            float t = l[e]; if (t > v1) { v1 = t; i1 = e; }
        }
        float e1v = __expf(v1 - v0);
        g_route[vg0 + tid] = (unsigned short)(i0 | (i1 << 8));
        g_prob[vg0 + tid]  = 1.f / (1.f + e1v);
    }

    // emit bf16 x rows [v][c] (reads conflict-free: bank = (c+v)%32, v consecutive)
    {
        const int vv = tid & 63, c0 = (tid >> 6) * 32;
        uint32_t pk[16];
        #pragma unroll
        for (int j = 0; j < 16; j++) {
            int c = c0 + 2 * j;
            __nv_bfloat162 t = __float22bfloat162_rn(
                make_float2(xs[c * VP + vv], xs[(c + 1) * VP + vv]));
            pk[j] = *(uint32_t*)&t;
        }
        uint4* dst = (uint4*)(g_xbt + ((size_t)(vg0 + vv)) * CDIM + c0);
        dst[0] = *(uint4*)&pk[0];
        dst[1] = *(uint4*)&pk[4];
        dst[2] = *(uint4*)&pk[8];
        dst[3] = *(uint4*)&pk[12];
    }
}

// ================= K2: bf16 mma.sync expert GEMMs =================
__global__ __launch_bounds__(256, 2)
void expert_kernel(const float* __restrict__ w1, const float* __restrict__ b1,
                   const float* __restrict__ w2, const float* __restrict__ b2)
{
    extern __shared__ char dynsm[];
    __shared__ unsigned short lst[CHUNK];
    __shared__ float b1s[CDIM], b2s[CDIM];
    __shared__ float pvs[SUBV];
    __shared__ int   gvs[SUBV];
    __shared__ int   sls[SUBV];
    __shared__ int   m_sh;

    const int tid = threadIdx.x;
    const int wid = tid >> 5, lane = tid & 31;
    const int chunk = blockIdx.x >> 3;
    const int e = blockIdx.x & 7;

    char* Ab  = dynsm;                 // A / H tile  [128 v][PKB]
    char* W1b = dynsm + 128 * PKB;
    char* W2b = dynsm + 256 * PKB;

    if (wid == 0) {    // ballot compaction (sorted list)
        int cnt = 0;
        for (int it = 0; it < CHUNK / 32; it++) {
            int v = it * 32 + lane;
            unsigned rt = g_route[chunk * CHUNK + v];
            bool h1 = ((rt >> 8) == (unsigned)e);
            bool hit = ((rt & 255u) == (unsigned)e) || h1;
            unsigned msk = __ballot_sync(0xFFFFFFFFu, hit);
            if (hit) lst[cnt + __popc(msk & ((1u << lane) - 1u))] =
                         (unsigned short)(v | (h1 ? 512 : 0));
            cnt += __popc(msk);
        }
        if (lane == 0) m_sh = cnt;
    }

    // stage W1, W2 (fp32 -> bf16, [o][k], pitch 272B)
    {
        int o = tid >> 1, kh = (tid & 1) * 64;
        const float4* s1 = (const float4*)(w1 + ((size_t)(e * CDIM + o)) * CDIM + kh);
        const float4* s2 = (const float4*)(w2 + ((size_t)(e * CDIM + o)) * CDIM + kh);
        char* d1 = W1b + o * PKB + kh * 2;
        char* d2 = W2b + o * PKB + kh * 2;
        #pragma unroll
        for (int j = 0; j < 16; j++) {
            float4 a = s1[j];
            uint2 v;
            __nv_bfloat162 t0 = __float22bfloat162_rn(make_float2(a.x, a.y));
            __nv_bfloat162 t1 = __float22bfloat162_rn(make_float2(a.z, a.w));
            v.x = *(uint32_t*)&t0; v.y = *(uint32_t*)&t1;
            *(uint2*)(d1 + 8 * j) = v;
            float4 c = s2[j];
            t0 = __float22bfloat162_rn(make_float2(c.x, c.y));
            t1 = __float22bfloat162_rn(make_float2(c.z, c.w));
            v.x = *(uint32_t*)&t0; v.y = *(uint32_t*)&t1;
            *(uint2*)(d2 + 8 * j) = v;
        }
    }
    if (tid < CDIM) {
        b1s[tid] = __ldg(b1 + e * CDIM + tid);
        b2s[tid] = __ldg(b2 + e * CDIM + tid);
    }
    __syncthreads();

    const int m = m_sh;
    if (m == 0) return;

    const uint32_t A_u  = smem_u32(Ab);
    const uint32_t W1_u = smem_u32(W1b);
    const uint32_t W2_u = smem_u32(W2b);

    const int warp_m = wid & 1, warp_n = wid >> 1;
    const uint32_t a_loff = (uint32_t)((lane & 15) * PKB + (lane >> 4) * 16);
    const uint32_t b_loff = (uint32_t)(((lane & 7) + ((lane >> 4) << 3)) * PKB +
                                       ((lane >> 3) & 1) * 16);
    const int rb = warp_m * 64 + (lane >> 2);
    const int cb = warp_n * 32 + 2 * (lane & 3);

    for (int bse = 0; bse < m; bse += SUBV) {
        const int msub = min(SUBV, m - bse);
        // per-warp active A-fragment count (tail-proportional work)
        int rem = msub - warp_m * 64;
        const int nmf = rem <= 0 ? 0 : (rem >= 64 ? 4 : ((rem + 15) >> 4));
        __syncthreads();

        // ---- gather x rows (bf16, contiguous 128B per half-row) ----
        {
            const int v = tid & 127, half = tid >> 7;
            if (v < msub) {
                int en2 = lst[bse + v];
                int slot = en2 >> 9;
                int gvox = chunk * CHUNK + (en2 & 511);
                if (half == 0) {
                    float p0 = g_prob[gvox];
                    pvs[v] = slot ? 1.f - p0 : p0;
                    gvs[v] = gvox; sls[v] = slot;
                }
                const uint4* src = (const uint4*)(g_xbt + ((size_t)gvox << 7) + (half << 6));
                uint4* dst = (uint4*)(Ab + v * PKB + half * 128);
                #pragma unroll
                for (int j = 0; j < 8; j++) dst[j] = src[j];
            }
        }
        __syncthreads();

        float acc[4][4][4];
        #pragma unroll
        for (int i = 0; i < 4; i++)
            #pragma unroll
            for (int j = 0; j < 4; j++)
                #pragma unroll
                for (int q = 0; q < 4; q++) acc[i][j][q] = 0.f;

        // ---- GEMM1 ----
        if (nmf > 0) {
            #pragma unroll
            for (int ks = 0; ks < 8; ks++) {
                const uint32_t kb = ks * 32;
                uint32_t af[4][4], bf[4][2];
                #pragma unroll
                for (int mf = 0; mf < 4; mf++) {
                    if (mf < nmf) {
                        uint32_t ad = A_u + (uint32_t)((warp_m * 64 + mf * 16) * PKB) + kb + a_loff;
                        LDSM_X4(af[mf][0], af[mf][1], af[mf][2], af[mf][3], ad);
                    }
                }
                #pragma unroll
                for (int np = 0; np < 2; np++) {
                    uint32_t bd = W1_u + (uint32_t)((warp_n * 32 + np * 16) * PKB) + kb + b_loff;
                    uint32_t r0, r1, r2, r3;
                    LDSM_X4(r0, r1, r2, r3, bd);
                    bf[2 * np][0] = r0; bf[2 * np][1] = r1;
                    bf[2 * np + 1][0] = r2; bf[2 * np + 1][1] = r3;
                }
                #pragma unroll
                for (int mf = 0; mf < 4; mf++)
                    if (mf < nmf)
                        #pragma unroll
                        for (int nf = 0; nf < 4; nf++)
                            MMA16816(acc[mf][nf], af[mf], bf[nf]);
            }
        }
        __syncthreads();

        // ---- epilogue 1: silu(+b1)*p -> bf16 H (reuse A tile) ----
        #pragma unroll
        for (int mf = 0; mf < 4; mf++) {
            if (mf < nmf) {
                int r0 = rb + mf * 16, r1 = r0 + 8;
                float p0 = pvs[r0], p1 = pvs[r1];
                #pragma unroll
                for (int nf = 0; nf < 4; nf++) {
                    int c = cb + nf * 8;
                    float bia0 = b1s[c], bia1 = b1s[c + 1];
                    float t0 = acc[mf][nf][0] + bia0, t1 = acc[mf][nf][1] + bia1;
                    float t2 = acc[mf][nf][2] + bia0, t3 = acc[mf][nf][3] + bia1;
                    float h0 = p0 * t0 / (1.f + __expf(-t0));
                    float h1 = p0 * t1 / (1.f + __expf(-t1));
                    float h2 = p1 * t2 / (1.f + __expf(-t2));
                    float h3 = p1 * t3 / (1.f + __expf(-t3));
                    __nv_bfloat162 u0 = __float22bfloat162_rn(make_float2(h0, h1));
                    __nv_bfloat162 u1 = __float22bfloat162_rn(make_float2(h2, h3));
                    *(uint32_t*)(Ab + r0 * PKB + c * 2) = *(uint32_t*)&u0;
                    *(uint32_t*)(Ab + r1 * PKB + c * 2) = *(uint32_t*)&u1;
                }
            }
        }
        __syncthreads();

        #pragma unroll
        for (int i = 0; i < 4; i++)
            #pragma unroll
            for (int j = 0; j < 4; j++)
                #pragma unroll
                for (int q = 0; q < 4; q++) acc[i][j][q] = 0.f;

        // ---- GEMM2 ----
        if (nmf > 0) {
            #pragma unroll
            for (int ks = 0; ks < 8; ks++) {
                const uint32_t kb = ks * 32;
                uint32_t af[4][4], bf[4][2];
                #pragma unroll
                for (int mf = 0; mf < 4; mf++) {
                    if (mf < nmf) {
                        uint32_t ad = A_u + (uint32_t)((warp_m * 64 + mf * 16) * PKB) + kb + a_loff;
                        LDSM_X4(af[mf][0], af[mf][1], af[mf][2], af[mf][3], ad);
                    }
                }
                #pragma unroll
                for (int np = 0; np < 2; np++) {
                    uint32_t bd = W2_u + (uint32_t)((warp_n * 32 + np * 16) * PKB) + kb + b_loff;
                    uint32_t r0, r1, r2, r3;
                    LDSM_X4(r0, r1, r2, r3, bd);
                    bf[2 * np][0] = r0; bf[2 * np][1] = r1;
                    bf[2 * np + 1][0] = r2; bf[2 * np + 1][1] = r3;
                }
                #pragma unroll
                for (int mf = 0; mf < 4; mf++)
                    if (mf < nmf)
                        #pragma unroll
                        for (int nf = 0; nf < 4; nf++)
                            MMA16816(acc[mf][nf], af[mf], bf[nf]);
            }
        }

        // ---- epilogue 2: +p*b2, bf16 scatter to y[slot] in [c][vglobal] ----
        #pragma unroll
        for (int mf = 0; mf < 4; mf++) {
            int r0 = rb + mf * 16;
            #pragma unroll
            for (int half = 0; half < 2; half++) {
                int r = r0 + half * 8;
                if (r < msub) {
                    float p = pvs[r];
                    int gvox = gvs[r];
                    __nv_bfloat16* yb = sls[r] ? g_y1h : g_y0h;
                    #pragma unroll
                    for (int nf = 0; nf < 4; nf++) {
                        int c = cb + nf * 8;
                        float o0 = acc[mf][nf][2 * half]     + p * b2s[c];
                        float o1 = acc[mf][nf][2 * half + 1] + p * b2s[c + 1];
                        yb[(size_t)c * NVOX + gvox]       = __float2bfloat16_rn(o0);
                        yb[(size_t)(c + 1) * NVOX + gvox] = __float2bfloat16_rn(o1);
                    }
                }
            }
        }
    }
}

// ================= K3: streaming combine out = x + y0 + y1 =================
__global__ __launch_bounds__(256)
void combine_kernel(const float* __restrict__ x, float* __restrict__ out)
{
    const size_t i = ((size_t)blockIdx.x * 256 + threadIdx.x) * 8;   // 8 floats per thread
    const int b = (int)(i >> 22);
    const int c = (int)((i >> 15) & 127);
    const int s = (int)(i & 32767);
    const size_t yoff = ((size_t)c << 16) + ((size_t)b << 15) + s;

    uint4 y0r = *(const uint4*)(g_y0h + yoff);
    uint4 y1r = *(const uint4*)(g_y1h + yoff);
    float4 x0 = *(const float4*)(x + i);
    float4 x1 = *(const float4*)(x + i + 4);

    const __nv_bfloat162* p0 = (const __nv_bfloat162*)&y0r;
    const __nv_bfloat162* p1 = (const __nv_bfloat162*)&y1r;
    float2 a0 = __bfloat1622float2(p0[0]), b0 = __bfloat1622float2(p1[0]);
    float2 a1 = __bfloat1622float2(p0[1]), b1 = __bfloat1622float2(p1[1]);
    float2 a2 = __bfloat1622float2(p0[2]), b2 = __bfloat1622float2(p1[2]);
    float2 a3 = __bfloat1622float2(p0[3]), b3 = __bfloat1622float2(p1[3]);

    float4 o0, o1;
    o0.x = x0.x + a0.x + b0.x;  o0.y = x0.y + a0.y + b0.y;
    o0.z = x0.z + a1.x + b1.x;  o0.w = x0.w + a1.y + b1.y;
    o1.x = x1.x + a2.x + b2.x;  o1.y = x1.y + a2.y + b2.y;
    o1.z = x1.z + a3.x + b3.x;  o1.w = x1.w + a3.y + b3.y;

    *(float4*)(out + i)     = o0;
    *(float4*)(out + i + 4) = o1;
}

// ================= launch =================
extern "C" void kernel_launch(void* const* d_in, const int* in_sizes, int n_in,
                              void* d_out, int out_size) {
    const float* x   = (const float*)d_in[0];
    const float* gwp = (const float*)d_in[1];
    const float* gbp = (const float*)d_in[2];
    const float* w1p = (const float*)d_in[3];
    const float* b1p = (const float*)d_in[4];
    const float* w2p = (const float*)d_in[5];
    const float* b2p = (const float*)d_in[6];
    float* outp = (float*)d_out;

    static int smem_set = 0;
    const int dyn_smem = 3 * 128 * PKB;   // 104448 B
    if (!smem_set) {
        cudaFuncSetAttribute(expert_kernel,
                             cudaFuncAttributeMaxDynamicSharedMemorySize, dyn_smem);
        smem_set = 1;
    }

    gate_kernel<<<NVOX / 64, 256>>>(x, gwp, gbp);
    expert_kernel<<<NCHUNK * NEXP, 256, dyn_smem>>>(w1p, b1p, w2p, b2p);
    combine_kernel<<<(NVOX * CDIM / 8) / 256, 256>>>(x, outp);
}

// round 6
// speedup vs baseline: 1.3035x; 1.3035x over previous
#include <cuda_runtime.h>
#include <cuda_bf16.h>
#include <cstdint>

#define CDIM    128
#define NEXP    8
#define SPATIAL 32768
#define NVOX    65536
#define CHUNK   512
#define NCHUNK  128
#define SUBV    128
#define PKB     272           // expert smem tile row pitch (bytes)
#define VP      68            // gate smem [c][v] pitch (floats, %4==0)
#define CP      65            // combine smem [c][v] pitch (floats)

// ---------------- device scratch ----------------
__device__ __nv_bfloat16 g_xbt[(size_t)NVOX * CDIM];   // x, bf16, [v][c]
__device__ __nv_bfloat16 g_y0h[(size_t)NVOX * CDIM];   // slot-0 y, bf16, [v][c]
__device__ __nv_bfloat16 g_y1h[(size_t)NVOX * CDIM];   // slot-1 y, bf16, [v][c]
__device__ unsigned short g_route[NVOX];
__device__ float          g_prob[NVOX];

__device__ __forceinline__ uint32_t smem_u32(const void* p) {
    uint32_t a;
    asm("{ .reg .u64 t; cvta.to.shared.u64 t, %1; cvt.u32.u64 %0, t; }" : "=r"(a) : "l"(p));
    return a;
}

#define LDSM_X4(r0, r1, r2, r3, addr) \
    asm volatile("ldmatrix.sync.aligned.m8n8.x4.shared.b16 {%0,%1,%2,%3}, [%4];" \
        : "=r"(r0), "=r"(r1), "=r"(r2), "=r"(r3) : "r"(addr))

#define MMA16816(c, a, b) \
    asm volatile("mma.sync.aligned.m16n8k16.row.col.f32.bf16.bf16.f32 " \
        "{%0,%1,%2,%3}, {%4,%5,%6,%7}, {%8,%9}, {%0,%1,%2,%3};" \
        : "+f"((c)[0]), "+f"((c)[1]), "+f"((c)[2]), "+f"((c)[3]) \
        : "r"((a)[0]), "r"((a)[1]), "r"((a)[2]), "r"((a)[3]), "r"((b)[0]), "r"((b)[1]))

// ================= K1: gate + bf16 xT emission =================
__global__ __launch_bounds__(256)
void gate_kernel(const float* __restrict__ x,
                 const float* __restrict__ gw,
                 const float* __restrict__ gb)
{
    __shared__ float xs[CDIM * VP];          // [c][v]
    __shared__ float gws[NEXP * CDIM];
    __shared__ float part[2][64 * NEXP];     // k-half partial logits

    const int tid = threadIdx.x;
    const int vg0 = blockIdx.x * 64;
    const int b = vg0 >> 15, s0 = vg0 & (SPATIAL - 1);
    const float* xb = x + ((size_t)b * CDIM) * SPATIAL + s0;

    for (int i = tid; i < NEXP * CDIM; i += 256) gws[i] = gw[i];

    const int c_sub = tid >> 6, iv = tid & 63;
    #pragma unroll
    for (int cc = 0; cc < CDIM; cc += 4) {
        int c = cc + c_sub;
        xs[c * VP + iv] = xb[(size_t)c * SPATIAL + iv];
    }
    __syncthreads();

    // logits: thread = (v-quad 16) x (expert 8) x (k-half 2)
    {
        const int vq = tid & 15;
        const int e  = (tid >> 4) & 7;
        const int kh = tid >> 7;
        const float* g0 = gws + e * CDIM + kh * 64;
        const float* xbase = xs + kh * 64 * VP + vq * 4;
        float4 acc = make_float4(0.f, 0.f, 0.f, 0.f);
        #pragma unroll 16
        for (int k = 0; k < 64; k++) {
            float4 xv = *(const float4*)(xbase + (size_t)k * VP);
            float w = g0[k];
            acc.x = fmaf(w, xv.x, acc.x);
            acc.y = fmaf(w, xv.y, acc.y);
            acc.z = fmaf(w, xv.z, acc.z);
            acc.w = fmaf(w, xv.w, acc.w);
        }
        part[kh][(vq * 4 + 0) * NEXP + e] = acc.x;
        part[kh][(vq * 4 + 1) * NEXP + e] = acc.y;
        part[kh][(vq * 4 + 2) * NEXP + e] = acc.z;
        part[kh][(vq * 4 + 3) * NEXP + e] = acc.w;
    }
    __syncthreads();

    if (tid < 64) {
        float l[NEXP];
        #pragma unroll
        for (int e = 0; e < NEXP; e++)
            l[e] = part[0][tid * NEXP + e] + part[1][tid * NEXP + e] + __ldg(gb + e);
        int i0 = 0; float v0 = l[0];
        #pragma unroll
        for (int e = 1; e < NEXP; e++) { float t = l[e]; if (t > v0) { v0 = t; i0 = e; } }
        int i1 = -1; float v1 = -3.4e38f;
        #pragma unroll
        for (int e = 0; e < NEXP; e++) {
            if (e == i0) continue;
            float t = l[e]; if (t > v1) { v1 = t; i1 = e; }
        }
        float e1v = __expf(v1 - v0);
        g_route[vg0 + tid] = (unsigned short)(i0 | (i1 << 8));
        g_prob[vg0 + tid]  = 1.f / (1.f + e1v);
    }

    // emit bf16 x rows [v][c]
    {
        const int vv = tid & 63, c0 = (tid >> 6) * 32;
        uint32_t pk[16];
        #pragma unroll
        for (int j = 0; j < 16; j++) {
            int c = c0 + 2 * j;
            __nv_bfloat162 t = __float22bfloat162_rn(
                make_float2(xs[c * VP + vv], xs[(c + 1) * VP + vv]));
            pk[j] = *(uint32_t*)&t;
        }
        uint4* dst = (uint4*)(g_xbt + ((size_t)(vg0 + vv)) * CDIM + c0);
        dst[0] = *(uint4*)&pk[0];
        dst[1] = *(uint4*)&pk[4];
        dst[2] = *(uint4*)&pk[8];
        dst[3] = *(uint4*)&pk[12];
    }
}

// ================= K2: bf16 mma.sync expert GEMMs =================
__global__ __launch_bounds__(256, 2)
void expert_kernel(const float* __restrict__ w1, const float* __restrict__ b1,
                   const float* __restrict__ w2, const float* __restrict__ b2)
{
    extern __shared__ char dynsm[];
    __shared__ unsigned short lst[CHUNK];
    __shared__ float b1s[CDIM], b2s[CDIM];
    __shared__ float pvs[SUBV];
    __shared__ int   gvs[SUBV];
    __shared__ int   sls[SUBV];
    __shared__ int   m_sh;

    const int tid = threadIdx.x;
    const int wid = tid >> 5, lane = tid & 31;
    const int chunk = blockIdx.x >> 3;
    const int e = blockIdx.x & 7;

    char* Ab  = dynsm;                 // A / H tile  [128 v][PKB]
    char* W1b = dynsm + 128 * PKB;
    char* W2b = dynsm + 256 * PKB;

    if (wid == 0) {    // ballot compaction (sorted list)
        int cnt = 0;
        for (int it = 0; it < CHUNK / 32; it++) {
            int v = it * 32 + lane;
            unsigned rt = g_route[chunk * CHUNK + v];
            bool h1 = ((rt >> 8) == (unsigned)e);
            bool hit = ((rt & 255u) == (unsigned)e) || h1;
            unsigned msk = __ballot_sync(0xFFFFFFFFu, hit);
            if (hit) lst[cnt + __popc(msk & ((1u << lane) - 1u))] =
                         (unsigned short)(v | (h1 ? 512 : 0));
            cnt += __popc(msk);
        }
        if (lane == 0) m_sh = cnt;
    }

    // stage W1, W2 (fp32 -> bf16, [o][k], pitch 272B)
    {
        int o = tid >> 1, kh = (tid & 1) * 64;
        const float4* s1 = (const float4*)(w1 + ((size_t)(e * CDIM + o)) * CDIM + kh);
        const float4* s2 = (const float4*)(w2 + ((size_t)(e * CDIM + o)) * CDIM + kh);
        char* d1 = W1b + o * PKB + kh * 2;
        char* d2 = W2b + o * PKB + kh * 2;
        #pragma unroll
        for (int j = 0; j < 16; j++) {
            float4 a = s1[j];
            uint2 v;
            __nv_bfloat162 t0 = __float22bfloat162_rn(make_float2(a.x, a.y));
            __nv_bfloat162 t1 = __float22bfloat162_rn(make_float2(a.z, a.w));
            v.x = *(uint32_t*)&t0; v.y = *(uint32_t*)&t1;
            *(uint2*)(d1 + 8 * j) = v;
            float4 c = s2[j];
            t0 = __float22bfloat162_rn(make_float2(c.x, c.y));
            t1 = __float22bfloat162_rn(make_float2(c.z, c.w));
            v.x = *(uint32_t*)&t0; v.y = *(uint32_t*)&t1;
            *(uint2*)(d2 + 8 * j) = v;
        }
    }
    if (tid < CDIM) {
        b1s[tid] = __ldg(b1 + e * CDIM + tid);
        b2s[tid] = __ldg(b2 + e * CDIM + tid);
    }
    __syncthreads();

    const int m = m_sh;
    if (m == 0) return;

    const uint32_t A_u  = smem_u32(Ab);
    const uint32_t W1_u = smem_u32(W1b);
    const uint32_t W2_u = smem_u32(W2b);

    const int warp_m = wid & 1, warp_n = wid >> 1;
    const uint32_t a_loff = (uint32_t)((lane & 15) * PKB + (lane >> 4) * 16);
    const uint32_t b_loff = (uint32_t)(((lane & 7) + ((lane >> 4) << 3)) * PKB +
                                       ((lane >> 3) & 1) * 16);
    const int rb = warp_m * 64 + (lane >> 2);
    const int cb = warp_n * 32 + 2 * (lane & 3);

    for (int bse = 0; bse < m; bse += SUBV) {
        const int msub = min(SUBV, m - bse);
        int rem = msub - warp_m * 64;
        const int nmf = rem <= 0 ? 0 : (rem >= 64 ? 4 : ((rem + 15) >> 4));
        __syncthreads();

        // ---- gather x rows (bf16, contiguous) ----
        {
            const int v = tid & 127, half = tid >> 7;
            if (v < msub) {
                int en2 = lst[bse + v];
                int slot = en2 >> 9;
                int gvox = chunk * CHUNK + (en2 & 511);
                if (half == 0) {
                    float p0 = g_prob[gvox];
                    pvs[v] = slot ? 1.f - p0 : p0;
                    gvs[v] = gvox; sls[v] = slot;
                }
                const uint4* src = (const uint4*)(g_xbt + ((size_t)gvox << 7) + (half << 6));
                uint4* dst = (uint4*)(Ab + v * PKB + half * 128);
                #pragma unroll
                for (int j = 0; j < 8; j++) dst[j] = src[j];
            }
        }
        __syncthreads();

        float acc[4][4][4];
        #pragma unroll
        for (int i = 0; i < 4; i++)
            #pragma unroll
            for (int j = 0; j < 4; j++)
                #pragma unroll
                for (int q = 0; q < 4; q++) acc[i][j][q] = 0.f;

        // ---- GEMM1 ----
        if (nmf > 0) {
            #pragma unroll
            for (int ks = 0; ks < 8; ks++) {
                const uint32_t kb = ks * 32;
                uint32_t af[4][4], bf[4][2];
                #pragma unroll
                for (int mf = 0; mf < 4; mf++) {
                    if (mf < nmf) {
                        uint32_t ad = A_u + (uint32_t)((warp_m * 64 + mf * 16) * PKB) + kb + a_loff;
                        LDSM_X4(af[mf][0], af[mf][1], af[mf][2], af[mf][3], ad);
                    }
                }
                #pragma unroll
                for (int np = 0; np < 2; np++) {
                    uint32_t bd = W1_u + (uint32_t)((warp_n * 32 + np * 16) * PKB) + kb + b_loff;
                    uint32_t r0, r1, r2, r3;
                    LDSM_X4(r0, r1, r2, r3, bd);
                    bf[2 * np][0] = r0; bf[2 * np][1] = r1;
                    bf[2 * np + 1][0] = r2; bf[2 * np + 1][1] = r3;
                }
                #pragma unroll
                for (int mf = 0; mf < 4; mf++)
                    if (mf < nmf)
                        #pragma unroll
                        for (int nf = 0; nf < 4; nf++)
                            MMA16816(acc[mf][nf], af[mf], bf[nf]);
            }
        }
        __syncthreads();

        // ---- epilogue 1: silu(+b1)*p -> bf16 H (reuse A tile) ----
        #pragma unroll
        for (int mf = 0; mf < 4; mf++) {
            if (mf < nmf) {
                int r0 = rb + mf * 16, r1 = r0 + 8;
                float p0 = pvs[r0], p1 = pvs[r1];
                #pragma unroll
                for (int nf = 0; nf < 4; nf++) {
                    int c = cb + nf * 8;
                    float bia0 = b1s[c], bia1 = b1s[c + 1];
                    float t0 = acc[mf][nf][0] + bia0, t1 = acc[mf][nf][1] + bia1;
                    float t2 = acc[mf][nf][2] + bia0, t3 = acc[mf][nf][3] + bia1;
                    float h0 = p0 * t0 * __fdividef(1.f, 1.f + __expf(-t0));
                    float h1 = p0 * t1 * __fdividef(1.f, 1.f + __expf(-t1));
                    float h2 = p1 * t2 * __fdividef(1.f, 1.f + __expf(-t2));
                    float h3 = p1 * t3 * __fdividef(1.f, 1.f + __expf(-t3));
                    __nv_bfloat162 u0 = __float22bfloat162_rn(make_float2(h0, h1));
                    __nv_bfloat162 u1 = __float22bfloat162_rn(make_float2(h2, h3));
                    *(uint32_t*)(Ab + r0 * PKB + c * 2) = *(uint32_t*)&u0;
                    *(uint32_t*)(Ab + r1 * PKB + c * 2) = *(uint32_t*)&u1;
                }
            }
        }
        __syncthreads();

        #pragma unroll
        for (int i = 0; i < 4; i++)
            #pragma unroll
            for (int j = 0; j < 4; j++)
                #pragma unroll
                for (int q = 0; q < 4; q++) acc[i][j][q] = 0.f;

        // ---- GEMM2 ----
        if (nmf > 0) {
            #pragma unroll
            for (int ks = 0; ks < 8; ks++) {
                const uint32_t kb = ks * 32;
                uint32_t af[4][4], bf[4][2];
                #pragma unroll
                for (int mf = 0; mf < 4; mf++) {
                    if (mf < nmf) {
                        uint32_t ad = A_u + (uint32_t)((warp_m * 64 + mf * 16) * PKB) + kb + a_loff;
                        LDSM_X4(af[mf][0], af[mf][1], af[mf][2], af[mf][3], ad);
                    }
                }
                #pragma unroll
                for (int np = 0; np < 2; np++) {
                    uint32_t bd = W2_u + (uint32_t)((warp_n * 32 + np * 16) * PKB) + kb + b_loff;
                    uint32_t r0, r1, r2, r3;
                    LDSM_X4(r0, r1, r2, r3, bd);
                    bf[2 * np][0] = r0; bf[2 * np][1] = r1;
                    bf[2 * np + 1][0] = r2; bf[2 * np + 1][1] = r3;
                }
                #pragma unroll
                for (int mf = 0; mf < 4; mf++)
                    if (mf < nmf)
                        #pragma unroll
                        for (int nf = 0; nf < 4; nf++)
                            MMA16816(acc[mf][nf], af[mf], bf[nf]);
            }
        }

        // ---- epilogue 2: +p*b2 -> bf16x2 stores, y[slot] voxel-major ----
        #pragma unroll
        for (int mf = 0; mf < 4; mf++) {
            int r0 = rb + mf * 16;
            #pragma unroll
            for (int half = 0; half < 2; half++) {
                int r = r0 + half * 8;
                if (r < msub) {
                    float p = pvs[r];
                    __nv_bfloat16* yb = (sls[r] ? g_y1h : g_y0h) + ((size_t)gvs[r] << 7);
                    #pragma unroll
                    for (int nf = 0; nf < 4; nf++) {
                        int c = cb + nf * 8;
                        float o0 = acc[mf][nf][2 * half]     + p * b2s[c];
                        float o1 = acc[mf][nf][2 * half + 1] + p * b2s[c + 1];
                        __nv_bfloat162 t = __float22bfloat162_rn(make_float2(o0, o1));
                        *(uint32_t*)(yb + c) = *(uint32_t*)&t;
                    }
                }
            }
        }
    }
}

// ================= K3: combine out = x + y0 + y1 (transpose) =================
__global__ __launch_bounds__(256)
void combine_kernel(const float* __restrict__ x, float* __restrict__ out)
{
    __shared__ float ts[CDIM * CP];
    const int tid = threadIdx.x;
    const int vg0 = blockIdx.x * 64;
    const int b = vg0 >> 15, s0 = vg0 & (SPATIAL - 1);

    const uint4* y04 = (const uint4*)(g_y0h + ((size_t)vg0 << 7));
    const uint4* y14 = (const uint4*)(g_y1h + ((size_t)vg0 << 7));
    #pragma unroll
    for (int j = 0; j < 4; j++) {
        int u = j * 256 + tid;          // 1024 uint4 = 64 vox * 128 ch
        int v = u >> 4;
        int c0 = (u & 15) * 8;
        uint4 a = y04[u], c = y14[u];
        const __nv_bfloat162* pa = (const __nv_bfloat162*)&a;
        const __nv_bfloat162* pc = (const __nv_bfloat162*)&c;
        #pragma unroll
        for (int q = 0; q < 4; q++) {
            float2 fa = __bfloat1622float2(pa[q]);
            float2 fc = __bfloat1622float2(pc[q]);
            ts[(c0 + 2 * q) * CP + v]     = fa.x + fc.x;
            ts[(c0 + 2 * q + 1) * CP + v] = fa.y + fc.y;
        }
    }
    __syncthreads();

    const int c_sub = tid >> 6, iv = tid & 63;
    const float* xb = x   + ((size_t)b * CDIM) * SPATIAL + s0;
    float*       ob = out + ((size_t)b * CDIM) * SPATIAL + s0;
    #pragma unroll
    for (int cc = 0; cc < CDIM; cc += 4) {
        int c = cc + c_sub;
        ob[(size_t)c * SPATIAL + iv] = ts[c * CP + iv] + xb[(size_t)c * SPATIAL + iv];
    }
}

// ================= launch =================
extern "C" void kernel_launch(void* const* d_in, const int* in_sizes, int n_in,
                              void* d_out, int out_size) {
    const float* x   = (const float*)d_in[0];
    const float* gwp = (const float*)d_in[1];
    const float* gbp = (const float*)d_in[2];
    const float* w1p = (const float*)d_in[3];
    const float* b1p = (const float*)d_in[4];
    const float* w2p = (const float*)d_in[5];
    const float* b2p = (const float*)d_in[6];
    float* outp = (float*)d_out;

    static int smem_set = 0;
    const int dyn_smem = 3 * 128 * PKB;   // 104448 B
    if (!smem_set) {
        cudaFuncSetAttribute(expert_kernel,
                             cudaFuncAttributeMaxDynamicSharedMemorySize, dyn_smem);
        smem_set = 1;
    }

    gate_kernel<<<NVOX / 64, 256>>>(x, gwp, gbp);
    expert_kernel<<<NCHUNK * NEXP, 256, dyn_smem>>>(w1p, b1p, w2p, b2p);
    combine_kernel<<<NVOX / 64, 256>>>(x, outp);
}

// round 7
// speedup vs baseline: 1.5581x; 1.1953x over previous
#include <cuda_runtime.h>
#include <cuda_bf16.h>
#include <cstdint>

#define CDIM    128
#define NEXP    8
#define SPATIAL 32768
#define NVOX    65536
#define CHUNK   1024
#define NCHUNK  (NVOX / CHUNK)   // 64
#define SUBV    128
#define PKB     272           // expert smem tile row pitch (bytes)
#define VP      68            // gate smem [c][v] pitch (floats, %4==0)
#define CP      65            // combine smem [c][v] pitch (floats)

// ---------------- device scratch ----------------
__device__ __nv_bfloat16 g_xbt[(size_t)NVOX * CDIM];   // x, bf16, [v][c]
__device__ __nv_bfloat16 g_y0h[(size_t)NVOX * CDIM];   // slot-0 y, bf16, [v][c]
__device__ __nv_bfloat16 g_y1h[(size_t)NVOX * CDIM];   // slot-1 y, bf16, [v][c]
__device__ unsigned short g_route[NVOX];
__device__ float          g_prob[NVOX];

__device__ __forceinline__ uint32_t smem_u32(const void* p) {
    uint32_t a;
    asm("{ .reg .u64 t; cvta.to.shared.u64 t, %1; cvt.u32.u64 %0, t; }" : "=r"(a) : "l"(p));
    return a;
}

#define LDSM_X4(r0, r1, r2, r3, addr) \
    asm volatile("ldmatrix.sync.aligned.m8n8.x4.shared.b16 {%0,%1,%2,%3}, [%4];" \
        : "=r"(r0), "=r"(r1), "=r"(r2), "=r"(r3) : "r"(addr))

#define MMA16816(c, a, b) \
    asm volatile("mma.sync.aligned.m16n8k16.row.col.f32.bf16.bf16.f32 " \
        "{%0,%1,%2,%3}, {%4,%5,%6,%7}, {%8,%9}, {%0,%1,%2,%3};" \
        : "+f"((c)[0]), "+f"((c)[1]), "+f"((c)[2]), "+f"((c)[3]) \
        : "r"((a)[0]), "r"((a)[1]), "r"((a)[2]), "r"((a)[3]), "r"((b)[0]), "r"((b)[1]))

#define CP_ASYNC16(dst, src) \
    asm volatile("cp.async.ca.shared.global [%0], [%1], 16;" :: "r"(dst), "l"(src))
#define CP_COMMIT() asm volatile("cp.async.commit_group;")
#define CP_WAIT0()  asm volatile("cp.async.wait_group 0;" ::: "memory")

// ================= K1: gate + bf16 xT emission =================
__global__ __launch_bounds__(256)
void gate_kernel(const float* __restrict__ x,
                 const float* __restrict__ gw,
                 const float* __restrict__ gb)
{
    __shared__ float xs[CDIM * VP];          // [c][v]
    __shared__ float gws[NEXP * CDIM];
    __shared__ float part[2][64 * NEXP];     // k-half partial logits

    const int tid = threadIdx.x;
    const int vg0 = blockIdx.x * 64;
    const int b = vg0 >> 15, s0 = vg0 & (SPATIAL - 1);
    const float* xb = x + ((size_t)b * CDIM) * SPATIAL + s0;

    for (int i = tid; i < NEXP * CDIM; i += 256) gws[i] = gw[i];

    // vectorized transpose load: thread = (c-slice 16, v-quad 16)
    {
        const int c16 = tid >> 4;            // 0..15
        const int v4  = (tid & 15) * 4;      // 0..60
        #pragma unroll
        for (int cc = 0; cc < CDIM; cc += 16) {
            int c = cc + c16;
            float4 xv = *(const float4*)(xb + (size_t)c * SPATIAL + v4);
            *(float4*)(xs + c * VP + v4) = xv;
        }
    }
    __syncthreads();

    // logits: thread = (v-quad 16) x (expert 8) x (k-half 2)
    {
        const int vq = tid & 15;
        const int e  = (tid >> 4) & 7;
        const int kh = tid >> 7;
        const float* g0 = gws + e * CDIM + kh * 64;
        const float* xbase = xs + kh * 64 * VP + vq * 4;
        float4 acc = make_float4(0.f, 0.f, 0.f, 0.f);
        #pragma unroll 16
        for (int k = 0; k < 64; k++) {
            float4 xv = *(const float4*)(xbase + (size_t)k * VP);
            float w = g0[k];
            acc.x = fmaf(w, xv.x, acc.x);
            acc.y = fmaf(w, xv.y, acc.y);
            acc.z = fmaf(w, xv.z, acc.z);
            acc.w = fmaf(w, xv.w, acc.w);
        }
        part[kh][(vq * 4 + 0) * NEXP + e] = acc.x;
        part[kh][(vq * 4 + 1) * NEXP + e] = acc.y;
        part[kh][(vq * 4 + 2) * NEXP + e] = acc.z;
        part[kh][(vq * 4 + 3) * NEXP + e] = acc.w;
    }
    __syncthreads();

    if (tid < 64) {
        float l[NEXP];
        #pragma unroll
        for (int e = 0; e < NEXP; e++)
            l[e] = part[0][tid * NEXP + e] + part[1][tid * NEXP + e] + __ldg(gb + e);
        int i0 = 0; float v0 = l[0];
        #pragma unroll
        for (int e = 1; e < NEXP; e++) { float t = l[e]; if (t > v0) { v0 = t; i0 = e; } }
        int i1 = -1; float v1 = -3.4e38f;
        #pragma unroll
        for (int e = 0; e < NEXP; e++) {
            if (e == i0) continue;
            float t = l[e]; if (t > v1) { v1 = t; i1 = e; }
        }
        float e1v = __expf(v1 - v0);
        g_route[vg0 + tid] = (unsigned short)(i0 | (i1 << 8));
        g_prob[vg0 + tid]  = 1.f / (1.f + e1v);
    }

    // emit bf16 x rows [v][c]
    {
        const int vv = tid & 63, c0 = (tid >> 6) * 32;
        uint32_t pk[16];
        #pragma unroll
        for (int j = 0; j < 16; j++) {
            int c = c0 + 2 * j;
            __nv_bfloat162 t = __float22bfloat162_rn(
                make_float2(xs[c * VP + vv], xs[(c + 1) * VP + vv]));
            pk[j] = *(uint32_t*)&t;
        }
        uint4* dst = (uint4*)(g_xbt + ((size_t)(vg0 + vv)) * CDIM + c0);
        dst[0] = *(uint4*)&pk[0];
        dst[1] = *(uint4*)&pk[4];
        dst[2] = *(uint4*)&pk[8];
        dst[3] = *(uint4*)&pk[12];
    }
}

// ================= K2: bf16 mma.sync expert GEMMs =================
__global__ __launch_bounds__(256, 2)
void expert_kernel(const float* __restrict__ w1, const float* __restrict__ b1,
                   const float* __restrict__ w2, const float* __restrict__ b2)
{
    extern __shared__ char dynsm[];
    __shared__ unsigned short lst[CHUNK];
    __shared__ float b1s[CDIM], b2s[CDIM];
    __shared__ float pvs[SUBV];
    __shared__ int   gvs[SUBV];
    __shared__ int   sls[SUBV];
    __shared__ int   m_sh;

    const int tid = threadIdx.x;
    const int wid = tid >> 5, lane = tid & 31;
    const int chunk = blockIdx.x >> 3;
    const int e = blockIdx.x & 7;

    char* Ab  = dynsm;                 // A / H tile  [128 v][PKB]
    char* W1b = dynsm + 128 * PKB;
    char* W2b = dynsm + 256 * PKB;

    if (wid == 0) {    // ballot compaction (sorted list), 32 iters
        int cnt = 0;
        for (int it = 0; it < CHUNK / 32; it++) {
            int v = it * 32 + lane;
            unsigned rt = g_route[chunk * CHUNK + v];
            bool h1 = ((rt >> 8) == (unsigned)e);
            bool hit = ((rt & 255u) == (unsigned)e) || h1;
            unsigned msk = __ballot_sync(0xFFFFFFFFu, hit);
            if (hit) lst[cnt + __popc(msk & ((1u << lane) - 1u))] =
                         (unsigned short)(v | (h1 ? CHUNK : 0));
            cnt += __popc(msk);
        }
        if (lane == 0) m_sh = cnt;
    }

    // stage W1, W2 (fp32 -> bf16, [o][k], pitch 272B)
    {
        int o = tid >> 1, kh = (tid & 1) * 64;
        const float4* s1 = (const float4*)(w1 + ((size_t)(e * CDIM + o)) * CDIM + kh);
        const float4* s2 = (const float4*)(w2 + ((size_t)(e * CDIM + o)) * CDIM + kh);
        char* d1 = W1b + o * PKB + kh * 2;
        char* d2 = W2b + o * PKB + kh * 2;
        #pragma unroll
        for (int j = 0; j < 16; j++) {
            float4 a = s1[j];
            uint2 v;
            __nv_bfloat162 t0 = __float22bfloat162_rn(make_float2(a.x, a.y));
            __nv_bfloat162 t1 = __float22bfloat162_rn(make_float2(a.z, a.w));
            v.x = *(uint32_t*)&t0; v.y = *(uint32_t*)&t1;
            *(uint2*)(d1 + 8 * j) = v;
            float4 c = s2[j];
            t0 = __float22bfloat162_rn(make_float2(c.x, c.y));
            t1 = __float22bfloat162_rn(make_float2(c.z, c.w));
            v.x = *(uint32_t*)&t0; v.y = *(uint32_t*)&t1;
            *(uint2*)(d2 + 8 * j) = v;
        }
    }
    if (tid < CDIM) {
        b1s[tid] = __ldg(b1 + e * CDIM + tid);
        b2s[tid] = __ldg(b2 + e * CDIM + tid);
    }
    __syncthreads();

    const int m = m_sh;
    if (m == 0) return;

    const uint32_t A_u  = smem_u32(Ab);
    const uint32_t W1_u = smem_u32(W1b);
    const uint32_t W2_u = smem_u32(W2b);

    const int warp_m = wid & 1, warp_n = wid >> 1;
    const uint32_t a_loff = (uint32_t)((lane & 15) * PKB + (lane >> 4) * 16);
    const uint32_t b_loff = (uint32_t)(((lane & 7) + ((lane >> 4) << 3)) * PKB +
                                       ((lane >> 3) & 1) * 16);
    const int rb = warp_m * 64 + (lane >> 2);
    const int cb = warp_n * 32 + 2 * (lane & 3);

    for (int bse = 0; bse < m; bse += SUBV) {
        const int msub = min(SUBV, m - bse);
        int rem = msub - warp_m * 64;
        const int nmf = rem <= 0 ? 0 : (rem >= 64 ? 4 : ((rem + 15) >> 4));
        __syncthreads();

        // ---- gather x rows via cp.async (contiguous 128B per half-row) ----
        {
            const int v = tid & 127, half = tid >> 7;
            if (v < msub) {
                int en2 = lst[bse + v];
                int slot = en2 >> 10;
                int gvox = chunk * CHUNK + (en2 & (CHUNK - 1));
                if (half == 0) {
                    float p0 = g_prob[gvox];
                    pvs[v] = slot ? 1.f - p0 : p0;
                    gvs[v] = gvox; sls[v] = slot;
                }
                const char* src = (const char*)(g_xbt + ((size_t)gvox << 7)) + (half << 7);
                uint32_t dst = A_u + (uint32_t)(v * PKB) + (half << 7);
                #pragma unroll
                for (int j = 0; j < 8; j++) CP_ASYNC16(dst + 16 * j, src + 16 * j);
            }
        }
        CP_COMMIT();
        CP_WAIT0();
        __syncthreads();

        float acc[4][4][4];
        #pragma unroll
        for (int i = 0; i < 4; i++)
            #pragma unroll
            for (int j = 0; j < 4; j++)
                #pragma unroll
                for (int q = 0; q < 4; q++) acc[i][j][q] = 0.f;

        // ---- GEMM1 ----
        if (nmf > 0) {
            #pragma unroll
            for (int ks = 0; ks < 8; ks++) {
                const uint32_t kb = ks * 32;
                uint32_t af[4][4], bf[4][2];
                #pragma unroll
                for (int mf = 0; mf < 4; mf++) {
                    if (mf < nmf) {
                        uint32_t ad = A_u + (uint32_t)((warp_m * 64 + mf * 16) * PKB) + kb + a_loff;
                        LDSM_X4(af[mf][0], af[mf][1], af[mf][2], af[mf][3], ad);
                    }
                }
                #pragma unroll
                for (int np = 0; np < 2; np++) {
                    uint32_t bd = W1_u + (uint32_t)((warp_n * 32 + np * 16) * PKB) + kb + b_loff;
                    uint32_t r0, r1, r2, r3;
                    LDSM_X4(r0, r1, r2, r3, bd);
                    bf[2 * np][0] = r0; bf[2 * np][1] = r1;
                    bf[2 * np + 1][0] = r2; bf[2 * np + 1][1] = r3;
                }
                #pragma unroll
                for (int mf = 0; mf < 4; mf++)
                    if (mf < nmf)
                        #pragma unroll
                        for (int nf = 0; nf < 4; nf++)
                            MMA16816(acc[mf][nf], af[mf], bf[nf]);
            }
        }
        __syncthreads();

        // ---- epilogue 1: silu(+b1)*p -> bf16 H (reuse A tile) ----
        #pragma unroll
        for (int mf = 0; mf < 4; mf++) {
            if (mf < nmf) {
                int r0 = rb + mf * 16, r1 = r0 + 8;
                float p0 = pvs[r0], p1 = pvs[r1];
                #pragma unroll
                for (int nf = 0; nf < 4; nf++) {
                    int c = cb + nf * 8;
                    float bia0 = b1s[c], bia1 = b1s[c + 1];
                    float t0 = acc[mf][nf][0] + bia0, t1 = acc[mf][nf][1] + bia1;
                    float t2 = acc[mf][nf][2] + bia0, t3 = acc[mf][nf][3] + bia1;
                    float h0 = p0 * t0 * __fdividef(1.f, 1.f + __expf(-t0));
                    float h1 = p0 * t1 * __fdividef(1.f, 1.f + __expf(-t1));
                    float h2 = p1 * t2 * __fdividef(1.f, 1.f + __expf(-t2));
                    float h3 = p1 * t3 * __fdividef(1.f, 1.f + __expf(-t3));
                    __nv_bfloat162 u0 = __float22bfloat162_rn(make_float2(h0, h1));
                    __nv_bfloat162 u1 = __float22bfloat162_rn(make_float2(h2, h3));
                    *(uint32_t*)(Ab + r0 * PKB + c * 2) = *(uint32_t*)&u0;
                    *(uint32_t*)(Ab + r1 * PKB + c * 2) = *(uint32_t*)&u1;
                }
            }
        }
        __syncthreads();

        #pragma unroll
        for (int i = 0; i < 4; i++)
            #pragma unroll
            for (int j = 0; j < 4; j++)
                #pragma unroll
                for (int q = 0; q < 4; q++) acc[i][j][q] = 0.f;

        // ---- GEMM2 ----
        if (nmf > 0) {
            #pragma unroll
            for (int ks = 0; ks < 8; ks++) {
                const uint32_t kb = ks * 32;
                uint32_t af[4][4], bf[4][2];
                #pragma unroll
                for (int mf = 0; mf < 4; mf++) {
                    if (mf < nmf) {
                        uint32_t ad = A_u + (uint32_t)((warp_m * 64 + mf * 16) * PKB) + kb + a_loff;
                        LDSM_X4(af[mf][0], af[mf][1], af[mf][2], af[mf][3], ad);
                    }
                }
                #pragma unroll
                for (int np = 0; np < 2; np++) {
                    uint32_t bd = W2_u + (uint32_t)((warp_n * 32 + np * 16) * PKB) + kb + b_loff;
                    uint32_t r0, r1, r2, r3;
                    LDSM_X4(r0, r1, r2, r3, bd);
                    bf[2 * np][0] = r0; bf[2 * np][1] = r1;
                    bf[2 * np + 1][0] = r2; bf[2 * np + 1][1] = r3;
                }
                #pragma unroll
                for (int mf = 0; mf < 4; mf++)
                    if (mf < nmf)
                        #pragma unroll
                        for (int nf = 0; nf < 4; nf++)
                            MMA16816(acc[mf][nf], af[mf], bf[nf]);
            }
        }

        // ---- epilogue 2: +p*b2 -> bf16x2 stores, y[slot] voxel-major ----
        #pragma unroll
        for (int mf = 0; mf < 4; mf++) {
            int r0 = rb + mf * 16;
            #pragma unroll
            for (int half = 0; half < 2; half++) {
                int r = r0 + half * 8;
                if (r < msub) {
                    float p = pvs[r];
                    __nv_bfloat16* yb = (sls[r] ? g_y1h : g_y0h) + ((size_t)gvs[r] << 7);
                    #pragma unroll
                    for (int nf = 0; nf < 4; nf++) {
                        int c = cb + nf * 8;
                        float o0 = acc[mf][nf][2 * half]     + p * b2s[c];
                        float o1 = acc[mf][nf][2 * half + 1] + p * b2s[c + 1];
                        __nv_bfloat162 t = __float22bfloat162_rn(make_float2(o0, o1));
                        *(uint32_t*)(yb + c) = *(uint32_t*)&t;
                    }
                }
            }
        }
    }
}

// ================= K3: combine out = x + y0 + y1 (transpose) =================
__global__ __launch_bounds__(256)
void combine_kernel(const float* __restrict__ x, float* __restrict__ out)
{
    __shared__ float ts[CDIM * CP];
    const int tid = threadIdx.x;
    const int vg0 = blockIdx.x * 64;
    const int b = vg0 >> 15, s0 = vg0 & (SPATIAL - 1);

    const uint4* y04 = (const uint4*)(g_y0h + ((size_t)vg0 << 7));
    const uint4* y14 = (const uint4*)(g_y1h + ((size_t)vg0 << 7));
    #pragma unroll
    for (int j = 0; j < 4; j++) {
        int u = j * 256 + tid;
        int v = u >> 4;
        int c0 = (u & 15) * 8;
        uint4 a = y04[u], c = y14[u];
        const __nv_bfloat162* pa = (const __nv_bfloat162*)&a;
        const __nv_bfloat162* pc = (const __nv_bfloat162*)&c;
        #pragma unroll
        for (int q = 0; q < 4; q++) {
            float2 fa = __bfloat1622float2(pa[q]);
            float2 fc = __bfloat1622float2(pc[q]);
            ts[(c0 + 2 * q) * CP + v]     = fa.x + fc.x;
            ts[(c0 + 2 * q + 1) * CP + v] = fa.y + fc.y;
        }
    }
    __syncthreads();

    const int c_sub = tid >> 6, iv = tid & 63;
    const float* xb = x   + ((size_t)b * CDIM) * SPATIAL + s0;
    float*       ob = out + ((size_t)b * CDIM) * SPATIAL + s0;
    #pragma unroll
    for (int cc = 0; cc < CDIM; cc += 4) {
        int c = cc + c_sub;
        ob[(size_t)c * SPATIAL + iv] = ts[c * CP + iv] + xb[(size_t)c * SPATIAL + iv];
    }
}

// ================= launch =================
extern "C" void kernel_launch(void* const* d_in, const int* in_sizes, int n_in,
                              void* d_out, int out_size) {
    const float* x   = (const float*)d_in[0];
    const float* gwp = (const float*)d_in[1];
    const float* gbp = (const float*)d_in[2];
    const float* w1p = (const float*)d_in[3];
    const float* b1p = (const float*)d_in[4];
    const float* w2p = (const float*)d_in[5];
    const float* b2p = (const float*)d_in[6];
    float* outp = (float*)d_out;

    static int smem_set = 0;
    const int dyn_smem = 3 * 128 * PKB;   // 104448 B
    if (!smem_set) {
        cudaFuncSetAttribute(expert_kernel,
                             cudaFuncAttributeMaxDynamicSharedMemorySize, dyn_smem);
        smem_set = 1;
    }

    gate_kernel<<<NVOX / 64, 256>>>(x, gwp, gbp);
    expert_kernel<<<NCHUNK * NEXP, 256, dyn_smem>>>(w1p, b1p, w2p, b2p);
    combine_kernel<<<NVOX / 64, 256>>>(x, outp);
}